// round 1
// baseline (speedup 1.0000x reference)
#include <cuda_runtime.h>
#include <cuda_bf16.h>
#include <cstdint>

// Problem shape (fixed by the dataset): N=100000 voxels, C=128 channels,
// K=27 offsets, M=50000 pairs per offset.
#define CCH 128
#define MAXELEM (100000 * 128)

__device__ float d_tmp1[MAXELEM];   // conv1 raw output
__device__ float d_tmp2[MAXELEM];   // conv2 raw output
__device__ float d_stats[512];      // [0:256) BN1 {sum,sumsq}, [256:512) BN2
__device__ float d_bnsb[512];       // [0:256) BN1 {scale,bias}, [256:512) BN2

// ---------------------------------------------------------------------------
// helpers
// ---------------------------------------------------------------------------
__device__ __forceinline__ float tf32r(float x) {
    uint32_t u;
    asm("cvt.rna.tf32.f32 %0, %1;" : "=r"(u) : "f"(x));
    return __uint_as_float(u);
}

__device__ __forceinline__ void mma_tf32(float* d, const uint32_t* a, const uint32_t* b) {
    asm volatile(
        "mma.sync.aligned.m16n8k8.row.col.f32.tf32.tf32.f32 "
        "{%0,%1,%2,%3}, {%4,%5,%6,%7}, {%8,%9}, {%0,%1,%2,%3};"
        : "+f"(d[0]), "+f"(d[1]), "+f"(d[2]), "+f"(d[3])
        : "r"(a[0]), "r"(a[1]), "r"(a[2]), "r"(a[3]), "r"(b[0]), "r"(b[1]));
}

__device__ __forceinline__ void red4(float* p, float4 v) {
    asm volatile("red.global.add.v4.f32 [%0], {%1,%2,%3,%4};"
                 :: "l"(p), "f"(v.x), "f"(v.y), "f"(v.z), "f"(v.w)
                 : "memory");
}

// ---------------------------------------------------------------------------
// fused gather -> tf32 GEMM -> scatter-add conv
// block: 256 threads, tile = 128 pair-rows x 128 cout, full 128 cin
// smem: As[128][132] gathered act, Ws[128][133] weights transposed [cout][cin]
// sb != null: apply per-channel scale/bias + ReLU to gathered rows (fused BN)
// ---------------------------------------------------------------------------
#define AS 132
#define WS 133
#define CONV_SMEM ((128 * AS + 128 * WS) * 4 + 256 * 4)

__global__ __launch_bounds__(256, 1)
void conv_kernel(const float* __restrict__ x, const float* __restrict__ w,
                 const int* __restrict__ idx_in, const int* __restrict__ idx_out,
                 float* __restrict__ out, int M,
                 const float* __restrict__ sb)
{
    extern __shared__ float smem[];
    float* Asm = smem;                       // 128*132 floats
    float* Wsm = smem + 128 * AS;            // 128*133 floats
    int*   II  = (int*)(Wsm + 128 * WS);     // 128 ints
    int*   IO  = II + 128;                   // 128 ints

    const int k   = blockIdx.y;
    const int m0  = blockIdx.x * 128;
    const int tid = threadIdx.x;

    // pair indices for this tile (-1 = out of range)
    for (int i = tid; i < 128; i += 256) {
        int m = m0 + i;
        II[i] = (m < M) ? idx_in [k * M + m] : -1;
        IO[i] = (m < M) ? idx_out[k * M + m] : -1;
    }

    // weights: transpose to [cout][cin], tf32-round. global read coalesced.
    const float* wk = w + k * (CCH * CCH);
    for (int i = tid; i < CCH * CCH; i += 256) {
        int cin = i >> 7, cout = i & 127;
        Wsm[cout * WS + cin] = tf32r(wk[i]);
    }
    __syncthreads();

    // gather activations (optionally BN+ReLU), tf32-round
    for (int i = tid; i < 128 * 32; i += 256) {
        int row = i >> 5, seg = i & 31;
        int src = II[row];
        float4 v = make_float4(0.f, 0.f, 0.f, 0.f);
        if (src >= 0) v = reinterpret_cast<const float4*>(x)[src * 32 + seg];
        if (sb) {
            int c = seg * 4;
            v.x = fmaxf(fmaf(v.x, sb[c + 0], sb[128 + c + 0]), 0.f);
            v.y = fmaxf(fmaf(v.y, sb[c + 1], sb[128 + c + 1]), 0.f);
            v.z = fmaxf(fmaf(v.z, sb[c + 2], sb[128 + c + 2]), 0.f);
            v.w = fmaxf(fmaf(v.w, sb[c + 3], sb[128 + c + 3]), 0.f);
        }
        v.x = tf32r(v.x); v.y = tf32r(v.y); v.z = tf32r(v.z); v.w = tf32r(v.w);
        *reinterpret_cast<float4*>(&Asm[row * AS + seg * 4]) = v;
    }
    __syncthreads();

    const int lane = tid & 31;
    const int warp = tid >> 5;
    const int wm = warp & 3;   // 4 warps over M (32 rows each)
    const int wn = warp >> 2;  // 2 warps over N (64 cols each)

    float acc[2][8][4];
    #pragma unroll
    for (int mf = 0; mf < 2; mf++)
        #pragma unroll
        for (int nf = 0; nf < 8; nf++)
            #pragma unroll
            for (int r = 0; r < 4; r++) acc[mf][nf][r] = 0.f;

    const int ar = wm * 32 + (lane >> 2);
    const int ac = lane & 3;
    const int bn = wn * 64 + (lane >> 2);
    const int bk = lane & 3;

    #pragma unroll
    for (int kk = 0; kk < CCH; kk += 8) {
        uint32_t a[2][4];
        #pragma unroll
        for (int mf = 0; mf < 2; mf++) {
            const float* ap = &Asm[(ar + mf * 16) * AS + kk + ac];
            a[mf][0] = __float_as_uint(ap[0]);
            a[mf][1] = __float_as_uint(ap[8 * AS]);
            a[mf][2] = __float_as_uint(ap[4]);
            a[mf][3] = __float_as_uint(ap[8 * AS + 4]);
        }
        uint32_t b[8][2];
        #pragma unroll
        for (int nf = 0; nf < 8; nf++) {
            const float* bp = &Wsm[(bn + nf * 8) * WS + kk + bk];
            b[nf][0] = __float_as_uint(bp[0]);
            b[nf][1] = __float_as_uint(bp[4]);
        }
        #pragma unroll
        for (int mf = 0; mf < 2; mf++)
            #pragma unroll
            for (int nf = 0; nf < 8; nf++)
                mma_tf32(acc[mf][nf], a[mf], b[nf]);
    }

    // stage results through SMEM (reuse A tile) so scatter is float4-vectorized
    __syncthreads();
    #pragma unroll
    for (int mf = 0; mf < 2; mf++) {
        #pragma unroll
        for (int nf = 0; nf < 8; nf++) {
            int r = wm * 32 + mf * 16 + (lane >> 2);
            int c = wn * 64 + nf * 8 + (lane & 3) * 2;
            *reinterpret_cast<float2*>(&Asm[r * AS + c])       = make_float2(acc[mf][nf][0], acc[mf][nf][1]);
            *reinterpret_cast<float2*>(&Asm[(r + 8) * AS + c]) = make_float2(acc[mf][nf][2], acc[mf][nf][3]);
        }
    }
    __syncthreads();

    // scatter-add: 16B vector reductions into L2
    for (int i = tid; i < 128 * 32; i += 256) {
        int row = i >> 5, seg = i & 31;
        int dst = IO[row];
        if (dst >= 0) {
            float4 v = *reinterpret_cast<float4*>(&Asm[row * AS + seg * 4]);
            red4(&out[dst * CCH + seg * 4], v);
        }
    }
}

// ---------------------------------------------------------------------------
// BN batch stats: per-channel sum and sum of squares
// ---------------------------------------------------------------------------
__global__ void bn_stats(const float* __restrict__ t, int N, float* __restrict__ stats)
{
    __shared__ float sh[256], sh2[256];
    const int c    = threadIdx.x & 127;
    const int half = threadIdx.x >> 7;
    float s = 0.f, s2 = 0.f;
    for (int r = blockIdx.x * 2 + half; r < N; r += gridDim.x * 2) {
        float v = t[r * CCH + c];
        s += v;
        s2 = fmaf(v, v, s2);
    }
    sh[threadIdx.x] = s; sh2[threadIdx.x] = s2;
    __syncthreads();
    if (threadIdx.x < 128) {
        atomicAdd(&stats[c],       sh[threadIdx.x] + sh[threadIdx.x + 128]);
        atomicAdd(&stats[128 + c], sh2[threadIdx.x] + sh2[threadIdx.x + 128]);
    }
}

__global__ void bn_finalize(const float* __restrict__ stats,
                            const float* __restrict__ gamma,
                            const float* __restrict__ beta,
                            float* __restrict__ sb, float invN)
{
    int c = threadIdx.x;  // 128 threads
    float mean = stats[c] * invN;
    float var  = stats[128 + c] * invN - mean * mean;
    float s    = gamma[c] * rsqrtf(var + 1e-5f);
    sb[c]       = s;
    sb[128 + c] = beta[c] - mean * s;
}

// ---------------------------------------------------------------------------
// final: out = relu(bn2(conv2) + identity)
// ---------------------------------------------------------------------------
__global__ void final_kernel(const float* __restrict__ t2, const float* __restrict__ x,
                             const float* __restrict__ sb, float* __restrict__ out,
                             int total4)
{
    int i = blockIdx.x * blockDim.x + threadIdx.x;
    if (i >= total4) return;
    float4 v  = reinterpret_cast<const float4*>(t2)[i];
    float4 xi = reinterpret_cast<const float4*>(x)[i];
    int c = (i & 31) * 4;
    float4 o;
    o.x = fmaxf(fmaf(v.x, sb[c + 0], sb[128 + c + 0]) + xi.x, 0.f);
    o.y = fmaxf(fmaf(v.y, sb[c + 1], sb[128 + c + 1]) + xi.y, 0.f);
    o.z = fmaxf(fmaf(v.z, sb[c + 2], sb[128 + c + 2]) + xi.z, 0.f);
    o.w = fmaxf(fmaf(v.w, sb[c + 3], sb[128 + c + 3]) + xi.w, 0.f);
    reinterpret_cast<float4*>(out)[i] = o;
}

// ---------------------------------------------------------------------------
// launch
// ---------------------------------------------------------------------------
extern "C" void kernel_launch(void* const* d_in, const int* in_sizes, int n_in,
                              void* d_out, int out_size)
{
    const float* x      = (const float*)d_in[0];
    const float* w1     = (const float*)d_in[1];
    const float* gamma1 = (const float*)d_in[2];
    const float* beta1  = (const float*)d_in[3];
    const float* w2     = (const float*)d_in[4];
    const float* gamma2 = (const float*)d_in[5];
    const float* beta2  = (const float*)d_in[6];
    const int*   idx_in  = (const int*)d_in[7];
    const int*   idx_out = (const int*)d_in[8];
    float* out = (float*)d_out;

    const int N = in_sizes[0] / CCH;           // 100000
    const int K = in_sizes[1] / (CCH * CCH);   // 27
    const int M = in_sizes[7] / K;             // 50000

    cudaStream_t s = 0;

    float *tmp1, *tmp2, *stats, *bnsb;
    cudaGetSymbolAddress((void**)&tmp1,  d_tmp1);
    cudaGetSymbolAddress((void**)&tmp2,  d_tmp2);
    cudaGetSymbolAddress((void**)&stats, d_stats);
    cudaGetSymbolAddress((void**)&bnsb,  d_bnsb);

    size_t nb = (size_t)N * CCH * sizeof(float);
    cudaMemsetAsync(tmp1, 0, nb, s);
    cudaMemsetAsync(tmp2, 0, nb, s);
    cudaMemsetAsync(stats, 0, 512 * sizeof(float), s);

    cudaFuncSetAttribute(conv_kernel, cudaFuncAttributeMaxDynamicSharedMemorySize, CONV_SMEM);

    dim3 grid((M + 127) / 128, K);
    float invN = 1.0f / (float)N;

    // conv1 -> BN1 params
    conv_kernel<<<grid, 256, CONV_SMEM, s>>>(x, w1, idx_in, idx_out, tmp1, M, nullptr);
    bn_stats<<<148, 256, 0, s>>>(tmp1, N, stats);
    bn_finalize<<<1, 128, 0, s>>>(stats, gamma1, beta1, bnsb, invN);

    // conv2 (BN1+ReLU fused into gather) -> BN2 params
    conv_kernel<<<grid, 256, CONV_SMEM, s>>>(tmp1, w2, idx_in, idx_out, tmp2, M, bnsb);
    bn_stats<<<148, 256, 0, s>>>(tmp2, N, stats + 256);
    bn_finalize<<<1, 128, 0, s>>>(stats + 256, gamma2, beta2, bnsb + 256, invN);

    // residual epilogue
    int total4 = N * (CCH / 4);
    final_kernel<<<(total4 + 255) / 256, 256, 0, s>>>(tmp2, x, bnsb + 256, out, total4);
}

// round 2
// speedup vs baseline: 1.4723x; 1.4723x over previous
#include <cuda_runtime.h>
#include <cuda_bf16.h>
#include <cstdint>

// Problem shape (fixed by the dataset): N=100000 voxels, C=128 channels,
// K=27 offsets, M=50000 pairs per offset.
#define CCH 128
#define MAXELEM (100000 * 128)

__device__ float d_tmp1[MAXELEM];   // conv1 raw output
__device__ float d_tmp2[MAXELEM];   // conv2 raw output
__device__ float d_stats[512];      // [0:256) BN1 {sum,sumsq}, [256:512) BN2
__device__ float d_bnsb[512];       // [0:256) BN1 {scale,bias}, [256:512) BN2

// ---------------------------------------------------------------------------
// helpers
// ---------------------------------------------------------------------------
__device__ __forceinline__ float tf32r(float x) {
    uint32_t u;
    asm("cvt.rna.tf32.f32 %0, %1;" : "=r"(u) : "f"(x));
    return __uint_as_float(u);
}

__device__ __forceinline__ void mma_tf32(float* d, const uint32_t* a, const uint32_t* b) {
    asm volatile(
        "mma.sync.aligned.m16n8k8.row.col.f32.tf32.tf32.f32 "
        "{%0,%1,%2,%3}, {%4,%5,%6,%7}, {%8,%9}, {%0,%1,%2,%3};"
        : "+f"(d[0]), "+f"(d[1]), "+f"(d[2]), "+f"(d[3])
        : "r"(a[0]), "r"(a[1]), "r"(a[2]), "r"(a[3]), "r"(b[0]), "r"(b[1]));
}

__device__ __forceinline__ void red4(float* p, float4 v) {
    asm volatile("red.global.add.v4.f32 [%0], {%1,%2,%3,%4};"
                 :: "l"(p), "f"(v.x), "f"(v.y), "f"(v.z), "f"(v.w)
                 : "memory");
}

// ---------------------------------------------------------------------------
// fused gather -> tf32 GEMM -> scatter-add conv
// block: 512 threads (16 warps), tile = 256 pair-rows x 128 cout, full 128 cin
// warps: wm in [0,8) covers 32 rows each; wn in [0,2) covers 64 cols each
// smem: As[256][132] gathered act, Ws[128][133] weights transposed [cout][cin]
// sb != null: apply per-channel scale/bias + ReLU to gathered rows (fused BN)
// ---------------------------------------------------------------------------
#define TILE_M 256
#define AS 132
#define WS 133
#define CONV_SMEM ((TILE_M * AS + 128 * WS) * 4 + 2 * TILE_M * 4)

__global__ __launch_bounds__(512, 1)
void conv_kernel(const float* __restrict__ x, const float* __restrict__ w,
                 const int* __restrict__ idx_in, const int* __restrict__ idx_out,
                 float* __restrict__ out, int M,
                 const float* __restrict__ sb)
{
    extern __shared__ float smem[];
    float* Asm = smem;                        // TILE_M*132 floats
    float* Wsm = smem + TILE_M * AS;          // 128*133 floats
    int*   II  = (int*)(Wsm + 128 * WS);      // TILE_M ints
    int*   IO  = II + TILE_M;                 // TILE_M ints

    const int k   = blockIdx.y;
    const int m0  = blockIdx.x * TILE_M;
    const int tid = threadIdx.x;

    // pair indices for this tile (-1 = out of range)
    for (int i = tid; i < TILE_M; i += 512) {
        int m = m0 + i;
        II[i] = (m < M) ? idx_in [k * M + m] : -1;
        IO[i] = (m < M) ? idx_out[k * M + m] : -1;
    }

    // weights: transpose to [cout][cin], tf32-round. global read coalesced.
    const float* wk = w + k * (CCH * CCH);
    for (int i = tid; i < CCH * CCH; i += 512) {
        int cin = i >> 7, cout = i & 127;
        Wsm[cout * WS + cin] = tf32r(wk[i]);
    }
    __syncthreads();

    // gather activations (optionally BN+ReLU), tf32-round
    for (int i = tid; i < TILE_M * 32; i += 512) {
        int row = i >> 5, seg = i & 31;
        int src = II[row];
        float4 v = make_float4(0.f, 0.f, 0.f, 0.f);
        if (src >= 0) v = reinterpret_cast<const float4*>(x)[src * 32 + seg];
        if (sb) {
            int c = seg * 4;
            v.x = fmaxf(fmaf(v.x, sb[c + 0], sb[128 + c + 0]), 0.f);
            v.y = fmaxf(fmaf(v.y, sb[c + 1], sb[128 + c + 1]), 0.f);
            v.z = fmaxf(fmaf(v.z, sb[c + 2], sb[128 + c + 2]), 0.f);
            v.w = fmaxf(fmaf(v.w, sb[c + 3], sb[128 + c + 3]), 0.f);
        }
        v.x = tf32r(v.x); v.y = tf32r(v.y); v.z = tf32r(v.z); v.w = tf32r(v.w);
        *reinterpret_cast<float4*>(&Asm[row * AS + seg * 4]) = v;
    }
    __syncthreads();

    const int lane = tid & 31;
    const int warp = tid >> 5;
    const int wm = warp & 7;   // 8 warps over M (32 rows each -> 256)
    const int wn = warp >> 3;  // 2 warps over N (64 cols each)

    float acc[2][8][4];
    #pragma unroll
    for (int mf = 0; mf < 2; mf++)
        #pragma unroll
        for (int nf = 0; nf < 8; nf++)
            #pragma unroll
            for (int r = 0; r < 4; r++) acc[mf][nf][r] = 0.f;

    const int ar = wm * 32 + (lane >> 2);
    const int ac = lane & 3;
    const int bn = wn * 64 + (lane >> 2);
    const int bk = lane & 3;

    #pragma unroll
    for (int kk = 0; kk < CCH; kk += 8) {
        uint32_t a[2][4];
        #pragma unroll
        for (int mf = 0; mf < 2; mf++) {
            const float* ap = &Asm[(ar + mf * 16) * AS + kk + ac];
            a[mf][0] = __float_as_uint(ap[0]);
            a[mf][1] = __float_as_uint(ap[8 * AS]);
            a[mf][2] = __float_as_uint(ap[4]);
            a[mf][3] = __float_as_uint(ap[8 * AS + 4]);
        }
        uint32_t b[8][2];
        #pragma unroll
        for (int nf = 0; nf < 8; nf++) {
            const float* bp = &Wsm[(bn + nf * 8) * WS + kk + bk];
            b[nf][0] = __float_as_uint(bp[0]);
            b[nf][1] = __float_as_uint(bp[4]);
        }
        #pragma unroll
        for (int mf = 0; mf < 2; mf++)
            #pragma unroll
            for (int nf = 0; nf < 8; nf++)
                mma_tf32(acc[mf][nf], a[mf], b[nf]);
    }

    // stage results through SMEM (reuse A tile) so scatter is float4-vectorized
    __syncthreads();
    #pragma unroll
    for (int mf = 0; mf < 2; mf++) {
        #pragma unroll
        for (int nf = 0; nf < 8; nf++) {
            int r = wm * 32 + mf * 16 + (lane >> 2);
            int c = wn * 64 + nf * 8 + (lane & 3) * 2;
            *reinterpret_cast<float2*>(&Asm[r * AS + c])       = make_float2(acc[mf][nf][0], acc[mf][nf][1]);
            *reinterpret_cast<float2*>(&Asm[(r + 8) * AS + c]) = make_float2(acc[mf][nf][2], acc[mf][nf][3]);
        }
    }
    __syncthreads();

    // scatter-add: 16B vector reductions into L2
    for (int i = tid; i < TILE_M * 32; i += 512) {
        int row = i >> 5, seg = i & 31;
        int dst = IO[row];
        if (dst >= 0) {
            float4 v = *reinterpret_cast<float4*>(&Asm[row * AS + seg * 4]);
            red4(&out[dst * CCH + seg * 4], v);
        }
    }
}

// ---------------------------------------------------------------------------
// BN batch stats: per-channel sum and sum of squares
// ---------------------------------------------------------------------------
__global__ void bn_stats(const float* __restrict__ t, int N, float* __restrict__ stats)
{
    __shared__ float sh[256], sh2[256];
    const int c    = threadIdx.x & 127;
    const int half = threadIdx.x >> 7;
    float s = 0.f, s2 = 0.f;
    for (int r = blockIdx.x * 2 + half; r < N; r += gridDim.x * 2) {
        float v = t[r * CCH + c];
        s += v;
        s2 = fmaf(v, v, s2);
    }
    sh[threadIdx.x] = s; sh2[threadIdx.x] = s2;
    __syncthreads();
    if (threadIdx.x < 128) {
        atomicAdd(&stats[c],       sh[threadIdx.x] + sh[threadIdx.x + 128]);
        atomicAdd(&stats[128 + c], sh2[threadIdx.x] + sh2[threadIdx.x + 128]);
    }
}

__global__ void bn_finalize(const float* __restrict__ stats,
                            const float* __restrict__ gamma,
                            const float* __restrict__ beta,
                            float* __restrict__ sb, float invN)
{
    int c = threadIdx.x;  // 128 threads
    float mean = stats[c] * invN;
    float var  = stats[128 + c] * invN - mean * mean;
    float s    = gamma[c] * rsqrtf(var + 1e-5f);
    sb[c]       = s;
    sb[128 + c] = beta[c] - mean * s;
}

// ---------------------------------------------------------------------------
// final: out = relu(bn2(conv2) + identity)
// ---------------------------------------------------------------------------
__global__ void final_kernel(const float* __restrict__ t2, const float* __restrict__ x,
                             const float* __restrict__ sb, float* __restrict__ out,
                             int total4)
{
    int i = blockIdx.x * blockDim.x + threadIdx.x;
    if (i >= total4) return;
    float4 v  = reinterpret_cast<const float4*>(t2)[i];
    float4 xi = reinterpret_cast<const float4*>(x)[i];
    int c = (i & 31) * 4;
    float4 o;
    o.x = fmaxf(fmaf(v.x, sb[c + 0], sb[128 + c + 0]) + xi.x, 0.f);
    o.y = fmaxf(fmaf(v.y, sb[c + 1], sb[128 + c + 1]) + xi.y, 0.f);
    o.z = fmaxf(fmaf(v.z, sb[c + 2], sb[128 + c + 2]) + xi.z, 0.f);
    o.w = fmaxf(fmaf(v.w, sb[c + 3], sb[128 + c + 3]) + xi.w, 0.f);
    reinterpret_cast<float4*>(out)[i] = o;
}

// ---------------------------------------------------------------------------
// launch
// ---------------------------------------------------------------------------
extern "C" void kernel_launch(void* const* d_in, const int* in_sizes, int n_in,
                              void* d_out, int out_size)
{
    const float* x      = (const float*)d_in[0];
    const float* w1     = (const float*)d_in[1];
    const float* gamma1 = (const float*)d_in[2];
    const float* beta1  = (const float*)d_in[3];
    const float* w2     = (const float*)d_in[4];
    const float* gamma2 = (const float*)d_in[5];
    const float* beta2  = (const float*)d_in[6];
    const int*   idx_in  = (const int*)d_in[7];
    const int*   idx_out = (const int*)d_in[8];
    float* out = (float*)d_out;

    const int N = in_sizes[0] / CCH;           // 100000
    const int K = in_sizes[1] / (CCH * CCH);   // 27
    const int M = in_sizes[7] / K;             // 50000

    cudaStream_t s = 0;

    float *tmp1, *tmp2, *stats, *bnsb;
    cudaGetSymbolAddress((void**)&tmp1,  d_tmp1);
    cudaGetSymbolAddress((void**)&tmp2,  d_tmp2);
    cudaGetSymbolAddress((void**)&stats, d_stats);
    cudaGetSymbolAddress((void**)&bnsb,  d_bnsb);

    size_t nb = (size_t)N * CCH * sizeof(float);
    cudaMemsetAsync(tmp1, 0, nb, s);
    cudaMemsetAsync(tmp2, 0, nb, s);
    cudaMemsetAsync(stats, 0, 512 * sizeof(float), s);

    cudaFuncSetAttribute(conv_kernel, cudaFuncAttributeMaxDynamicSharedMemorySize, CONV_SMEM);

    dim3 grid((M + TILE_M - 1) / TILE_M, K);
    float invN = 1.0f / (float)N;

    // conv1 -> BN1 params
    conv_kernel<<<grid, 512, CONV_SMEM, s>>>(x, w1, idx_in, idx_out, tmp1, M, nullptr);
    bn_stats<<<148, 256, 0, s>>>(tmp1, N, stats);
    bn_finalize<<<1, 128, 0, s>>>(stats, gamma1, beta1, bnsb, invN);

    // conv2 (BN1+ReLU fused into gather) -> BN2 params
    conv_kernel<<<grid, 512, CONV_SMEM, s>>>(tmp1, w2, idx_in, idx_out, tmp2, M, bnsb);
    bn_stats<<<148, 256, 0, s>>>(tmp2, N, stats + 256);
    bn_finalize<<<1, 128, 0, s>>>(stats + 256, gamma2, beta2, bnsb + 256, invN);

    // residual epilogue
    int total4 = N * (CCH / 4);
    final_kernel<<<(total4 + 255) / 256, 256, 0, s>>>(tmp2, x, bnsb + 256, out, total4);
}

// round 4
// speedup vs baseline: 1.7039x; 1.1573x over previous
#include <cuda_runtime.h>
#include <cstdint>

// Problem shape (dataset-fixed): N=100000 voxels, C=128, K=27 offsets, M=50000 pairs.
#define CCH 128
#define MAXELEM (100000 * 128)

__device__ float d_tmp1[MAXELEM];   // conv1 raw output
__device__ float d_tmp2[MAXELEM];   // conv2 raw output
__device__ float d_xr[MAXELEM];     // tf32-rounded x (conv1 input)
__device__ float d_t1a[MAXELEM];    // tf32(relu(bn1(tmp1))) (conv2 input)
__device__ float d_stats[512];
__device__ float d_bnsb[512];

#define AS 132            // A tile row stride (floats), conflict-free scalar frags
#define WSTR 144          // W tile col stride (floats): 4 q-blocks x 36
#define A_FLOATS (128 * AS)
#define SMEM_FLOATS (2 * A_FLOATS + 128 * WSTR)
#define SMEM_BYTES (SMEM_FLOATS * 4)   // 208896 B

// ---------------- helpers ----------------
__device__ __forceinline__ float tf32r(float x) {
    uint32_t u; asm("cvt.rna.tf32.f32 %0, %1;" : "=r"(u) : "f"(x));
    return __uint_as_float(u);
}
__device__ __forceinline__ uint32_t s2u(const void* p) {
    uint32_t a;
    asm("{ .reg .u64 t; cvta.to.shared.u64 t, %1; cvt.u32.u64 %0, t; }" : "=r"(a) : "l"(p));
    return a;
}
__device__ __forceinline__ void mma_tf32(float* d, const uint32_t* a, uint32_t b0, uint32_t b1) {
    asm volatile(
        "mma.sync.aligned.m16n8k8.row.col.f32.tf32.tf32.f32 "
        "{%0,%1,%2,%3}, {%4,%5,%6,%7}, {%8,%9}, {%0,%1,%2,%3};"
        : "+f"(d[0]), "+f"(d[1]), "+f"(d[2]), "+f"(d[3])
        : "r"(a[0]), "r"(a[1]), "r"(a[2]), "r"(a[3]), "r"(b0), "r"(b1));
}
__device__ __forceinline__ void red4(float* p, float a, float b, float c, float d) {
    asm volatile("red.global.add.v4.f32 [%0], {%1,%2,%3,%4};"
                 :: "l"(p), "f"(a), "f"(b), "f"(c), "f"(d) : "memory");
}
__device__ __forceinline__ void cpa16(uint32_t dst, const void* src, int sbytes) {
    asm volatile("cp.async.cg.shared.global [%0], [%1], 16, %2;"
                 :: "r"(dst), "l"(src), "r"(sbytes) : "memory");
}

// ---------------------------------------------------------------------------
// persistent fused conv: cp.async double-buffered gather -> tf32 mma -> reg scatter
// 148 blocks x 512 threads; each block owns a contiguous range of 128-row tiles.
// A tiles: [128][AS] raw rows (pre-rounded input). W: [cout][q-permuted k] padded.
// ---------------------------------------------------------------------------
__global__ __launch_bounds__(512, 1)
void conv_tc(const float* __restrict__ x, const float* __restrict__ w,
             const int* __restrict__ idx_in, const int* __restrict__ idx_out,
             float* __restrict__ out, int M, int MT, int TT, int PER)
{
    extern __shared__ float sm[];
    float* Wsm = sm + 2 * A_FLOATS;
    const int tid = threadIdx.x, lane = tid & 31, warp = tid >> 5;

    int t0 = blockIdx.x * PER;
    int t1 = t0 + PER; if (t1 > TT) t1 = TT;
    if (t0 >= t1) return;

    const uint32_t a0u = s2u(sm), a1u = s2u(sm + A_FLOATS);

    auto issue_gather = [&](int t) {
        int k = t / MT, mt = t - k * MT, m0 = mt * 128;
        int nr = M - m0; if (nr > 128) nr = 128;
        const int* ii = idx_in + (size_t)k * M + m0;
        uint32_t ab = (t & 1) ? a1u : a0u;
        #pragma unroll
        for (int j = 0; j < 8; j++) {
            int id = tid + j * 512;
            int row = id >> 5, seg = id & 31;
            int ok = (row < nr);
            int src = ok ? __ldg(ii + row) : 0;
            cpa16(ab + (uint32_t)(row * AS + seg * 4) * 4,
                  x + (size_t)src * CCH + seg * 4, ok ? 16 : 0);
        }
        asm volatile("cp.async.commit_group;" ::: "memory");
    };

    issue_gather(t0);
    if (t0 + 1 < t1) issue_gather(t0 + 1);

    int kcur = -1;
    const int wm = warp & 3, wn = warp >> 2;   // 4x4 warp grid over 128x128
    const int gr = lane >> 2, tg = lane & 3;

    for (int i = t0; i < t1; i++) {
        int k = i / MT, mt = i - k * MT, m0 = mt * 128;
        int nr = M - m0; if (nr > 128) nr = 128;
        const float* Asm = (i & 1) ? (sm + A_FLOATS) : sm;

        if (i + 1 < t1) asm volatile("cp.async.wait_group 1;" ::: "memory");
        else            asm volatile("cp.async.wait_group 0;" ::: "memory");
        __syncthreads();

        if (k != kcur) {
            const float* wk = w + (size_t)k * (CCH * CCH);
            #pragma unroll 4
            for (int j = 0; j < 32; j++) {
                int idx = tid + j * 512;
                int cin = idx >> 7, cout = idx & 127;
                // q-permuted, padded: W[cout][ (cin&3)*36 + (cin>>2) ]
                Wsm[cout * WSTR + (cin & 3) * 36 + (cin >> 2)] = tf32r(wk[idx]);
            }
            kcur = k;
            __syncthreads();
        }

        float acc[2][4][4];
        #pragma unroll
        for (int a = 0; a < 2; a++)
            #pragma unroll
            for (int b = 0; b < 4; b++)
                #pragma unroll
                for (int c = 0; c < 4; c++) acc[a][b][c] = 0.f;

        const float* arow0 = Asm + (wm * 32 + gr) * AS;

        #pragma unroll
        for (int u = 0; u < 8; u++) {
            float4 bq[4];
            #pragma unroll
            for (int nf = 0; nf < 4; nf++)
                bq[nf] = *reinterpret_cast<const float4*>(
                    Wsm + (wn * 32 + nf * 8 + gr) * WSTR + tg * 36 + u * 4);
            #pragma unroll
            for (int v = 0; v < 2; v++) {
                int kk = (2 * u + v) * 8;
                uint32_t afr[2][4];
                #pragma unroll
                for (int mf = 0; mf < 2; mf++) {
                    const float* ap = arow0 + mf * 16 * AS + kk + tg;
                    afr[mf][0] = __float_as_uint(ap[0]);
                    afr[mf][1] = __float_as_uint(ap[8 * AS]);
                    afr[mf][2] = __float_as_uint(ap[4]);
                    afr[mf][3] = __float_as_uint(ap[8 * AS + 4]);
                }
                #pragma unroll
                for (int mf = 0; mf < 2; mf++)
                    #pragma unroll
                    for (int nf = 0; nf < 4; nf++) {
                        uint32_t b0 = __float_as_uint(v ? bq[nf].z : bq[nf].x);
                        uint32_t b1 = __float_as_uint(v ? bq[nf].w : bq[nf].y);
                        mma_tf32(acc[mf][nf], afr[mf], b0, b1);
                    }
            }
        }
        __syncthreads();   // all warps done reading Asm/Wsm

        if (i + 2 < t1) issue_gather(i + 2);

        // register-direct scatter: pair lanes via shuffle -> red.global.add.v4
        const int* io = idx_out + (size_t)k * M + m0;
        #pragma unroll
        for (int mf = 0; mf < 2; mf++) {
            #pragma unroll
            for (int rh = 0; rh < 2; rh++) {
                int r = wm * 32 + mf * 16 + rh * 8 + gr;
                int dst = (r < nr) ? __ldg(io + r) : -1;
                #pragma unroll
                for (int nf = 0; nf < 4; nf++) {
                    float c0 = acc[mf][nf][rh * 2 + 0];
                    float c1 = acc[mf][nf][rh * 2 + 1];
                    float q0 = __shfl_xor_sync(0xFFFFFFFFu, c0, 1);
                    float q1 = __shfl_xor_sync(0xFFFFFFFFu, c1, 1);
                    if (!(lane & 1) && dst >= 0) {
                        int col = wn * 32 + nf * 8 + (tg >> 1) * 4;
                        red4(out + (size_t)dst * CCH + col, c0, c1, q0, q1);
                    }
                }
            }
        }
    }
}

// ---------------- elementwise passes ----------------
__global__ void round_x(const float* __restrict__ in, float* __restrict__ o, int total4)
{
    int i = blockIdx.x * blockDim.x + threadIdx.x;
    if (i >= total4) return;
    float4 v = reinterpret_cast<const float4*>(in)[i];
    v.x = tf32r(v.x); v.y = tf32r(v.y); v.z = tf32r(v.z); v.w = tf32r(v.w);
    reinterpret_cast<float4*>(o)[i] = v;
}

__global__ void bn_apply(const float* __restrict__ t, const float* __restrict__ sb,
                         float* __restrict__ o, int total4)
{
    int i = blockIdx.x * blockDim.x + threadIdx.x;
    if (i >= total4) return;
    float4 v = reinterpret_cast<const float4*>(t)[i];
    int c = (i & 31) * 4;
    v.x = tf32r(fmaxf(fmaf(v.x, sb[c + 0], sb[128 + c + 0]), 0.f));
    v.y = tf32r(fmaxf(fmaf(v.y, sb[c + 1], sb[128 + c + 1]), 0.f));
    v.z = tf32r(fmaxf(fmaf(v.z, sb[c + 2], sb[128 + c + 2]), 0.f));
    v.w = tf32r(fmaxf(fmaf(v.w, sb[c + 3], sb[128 + c + 3]), 0.f));
    reinterpret_cast<float4*>(o)[i] = v;
}

__global__ void bn_stats(const float* __restrict__ t, int N, float* __restrict__ stats)
{
    __shared__ float sh[256], sh2[256];
    const int c = threadIdx.x & 127;
    const int half = threadIdx.x >> 7;
    float s = 0.f, s2 = 0.f;
    for (int r = blockIdx.x * 2 + half; r < N; r += gridDim.x * 2) {
        float v = t[r * CCH + c];
        s += v;
        s2 = fmaf(v, v, s2);
    }
    sh[threadIdx.x] = s; sh2[threadIdx.x] = s2;
    __syncthreads();
    if (threadIdx.x < 128) {
        atomicAdd(&stats[c],       sh[threadIdx.x] + sh[threadIdx.x + 128]);
        atomicAdd(&stats[128 + c], sh2[threadIdx.x] + sh2[threadIdx.x + 128]);
    }
}

__global__ void bn_finalize(const float* __restrict__ stats,
                            const float* __restrict__ gamma,
                            const float* __restrict__ beta,
                            float* __restrict__ sbout, float invN)
{
    int c = threadIdx.x;
    float mean = stats[c] * invN;
    float var  = stats[128 + c] * invN - mean * mean;
    float s    = gamma[c] * rsqrtf(var + 1e-5f);
    sbout[c]       = s;
    sbout[128 + c] = beta[c] - mean * s;
}

__global__ void final_kernel(const float* __restrict__ t2, const float* __restrict__ x,
                             const float* __restrict__ sbin, float* __restrict__ out,
                             int total4)
{
    int i = blockIdx.x * blockDim.x + threadIdx.x;
    if (i >= total4) return;
    float4 v  = reinterpret_cast<const float4*>(t2)[i];
    float4 xi = reinterpret_cast<const float4*>(x)[i];
    int c = (i & 31) * 4;
    float4 o;
    o.x = fmaxf(fmaf(v.x, sbin[c + 0], sbin[128 + c + 0]) + xi.x, 0.f);
    o.y = fmaxf(fmaf(v.y, sbin[c + 1], sbin[128 + c + 1]) + xi.y, 0.f);
    o.z = fmaxf(fmaf(v.z, sbin[c + 2], sbin[128 + c + 2]) + xi.z, 0.f);
    o.w = fmaxf(fmaf(v.w, sbin[c + 3], sbin[128 + c + 3]) + xi.w, 0.f);
    reinterpret_cast<float4*>(out)[i] = o;
}

// ---------------- launch ----------------
extern "C" void kernel_launch(void* const* d_in, const int* in_sizes, int n_in,
                              void* d_out, int out_size)
{
    const float* x      = (const float*)d_in[0];
    const float* w1     = (const float*)d_in[1];
    const float* gamma1 = (const float*)d_in[2];
    const float* beta1  = (const float*)d_in[3];
    const float* w2     = (const float*)d_in[4];
    const float* gamma2 = (const float*)d_in[5];
    const float* beta2  = (const float*)d_in[6];
    const int*   idx_in  = (const int*)d_in[7];
    const int*   idx_out = (const int*)d_in[8];
    float* out = (float*)d_out;

    const int N = in_sizes[0] / CCH;           // 100000
    const int K = in_sizes[1] / (CCH * CCH);   // 27
    const int M = in_sizes[7] / K;             // 50000
    const int MT = (M + 127) / 128;            // m-tiles per offset
    const int TT = K * MT;                     // total tiles
    const int GRID = 148;
    const int PER = (TT + GRID - 1) / GRID;

    cudaStream_t s = 0;

    float *tmp1, *tmp2, *xr, *t1a, *stats, *bnsb;
    cudaGetSymbolAddress((void**)&tmp1,  d_tmp1);
    cudaGetSymbolAddress((void**)&tmp2,  d_tmp2);
    cudaGetSymbolAddress((void**)&xr,    d_xr);
    cudaGetSymbolAddress((void**)&t1a,   d_t1a);
    cudaGetSymbolAddress((void**)&stats, d_stats);
    cudaGetSymbolAddress((void**)&bnsb,  d_bnsb);

    size_t nb = (size_t)N * CCH * sizeof(float);
    cudaMemsetAsync(tmp1, 0, nb, s);
    cudaMemsetAsync(tmp2, 0, nb, s);
    cudaMemsetAsync(stats, 0, 512 * sizeof(float), s);

    cudaFuncSetAttribute(conv_tc, cudaFuncAttributeMaxDynamicSharedMemorySize, SMEM_BYTES);

    const int total4 = N * (CCH / 4);
    const float invN = 1.0f / (float)N;

    // pre-round x for conv1 gathers
    round_x<<<(total4 + 255) / 256, 256, 0, s>>>(x, xr, total4);

    // conv1 -> BN1 params
    conv_tc<<<GRID, 512, SMEM_BYTES, s>>>(xr, w1, idx_in, idx_out, tmp1, M, MT, TT, PER);
    bn_stats<<<148, 256, 0, s>>>(tmp1, N, stats);
    bn_finalize<<<1, 128, 0, s>>>(stats, gamma1, beta1, bnsb, invN);

    // bn1 + relu + round -> conv2 input
    bn_apply<<<(total4 + 255) / 256, 256, 0, s>>>(tmp1, bnsb, t1a, total4);

    // conv2 -> BN2 params
    conv_tc<<<GRID, 512, SMEM_BYTES, s>>>(t1a, w2, idx_in, idx_out, tmp2, M, MT, TT, PER);
    bn_stats<<<148, 256, 0, s>>>(tmp2, N, stats + 256);
    bn_finalize<<<1, 128, 0, s>>>(stats + 256, gamma2, beta2, bnsb + 256, invN);

    // residual epilogue
    final_kernel<<<(total4 + 255) / 256, 256, 0, s>>>(tmp2, x, bnsb + 256, out, total4);
}

// round 6
// speedup vs baseline: 2.0034x; 1.1758x over previous
#include <cuda_runtime.h>
#include <cstdint>

// Problem shape (dataset-fixed): N=100000 voxels, C=128, K=27 offsets, M=50000 pairs.
#define CCH 128
#define MAXELEM (100000 * 128)

__device__ float d_tmp1[MAXELEM];   // conv1 raw output
__device__ float d_tmp2[MAXELEM];   // conv2 raw output
__device__ float d_t1a[MAXELEM];    // tf32(relu(bn1(tmp1))) (conv2 input)
__device__ float d_stats[512];
__device__ float d_bnsb[512];

#define AS 132            // A tile row stride (floats)
#define WSTR 144          // W tile col stride (floats): 4 q-blocks x 36
#define A_FLOATS (128 * AS)
#define W_FLOATS (128 * WSTR)
// idx ring: 8 slots x (128 idx_in + 128 idx_out) ints
#define IDX_INTS (8 * 256)
#define SMEM_FLOATS (2 * A_FLOATS + W_FLOATS + IDX_INTS)
#define SMEM_BYTES (SMEM_FLOATS * 4)   // 217088 B

// ---------------- helpers ----------------
__device__ __forceinline__ float tf32r(float x) {
    uint32_t u; asm("cvt.rna.tf32.f32 %0, %1;" : "=r"(u) : "f"(x));
    return __uint_as_float(u);
}
__device__ __forceinline__ uint32_t tf32ru(float x) {
    uint32_t u; asm("cvt.rna.tf32.f32 %0, %1;" : "=r"(u) : "f"(x));
    return u;
}
__device__ __forceinline__ uint32_t s2u(const void* p) {
    uint32_t a;
    asm("{ .reg .u64 t; cvta.to.shared.u64 t, %1; cvt.u32.u64 %0, t; }" : "=r"(a) : "l"(p));
    return a;
}
__device__ __forceinline__ void mma_tf32(float* d, const uint32_t* a, uint32_t b0, uint32_t b1) {
    asm volatile(
        "mma.sync.aligned.m16n8k8.row.col.f32.tf32.tf32.f32 "
        "{%0,%1,%2,%3}, {%4,%5,%6,%7}, {%8,%9}, {%0,%1,%2,%3};"
        : "+f"(d[0]), "+f"(d[1]), "+f"(d[2]), "+f"(d[3])
        : "r"(a[0]), "r"(a[1]), "r"(a[2]), "r"(a[3]), "r"(b0), "r"(b1));
}
__device__ __forceinline__ void red4(float* p, float a, float b, float c, float d) {
    asm volatile("red.global.add.v4.f32 [%0], {%1,%2,%3,%4};"
                 :: "l"(p), "f"(a), "f"(b), "f"(c), "f"(d) : "memory");
}
__device__ __forceinline__ void cpa16(uint32_t dst, const void* src, int sbytes) {
    asm volatile("cp.async.cg.shared.global [%0], [%1], 16, %2;"
                 :: "r"(dst), "l"(src), "r"(sbytes) : "memory");
}

// ---------------------------------------------------------------------------
// persistent fused conv: cp.async double-buffered gather + 8-slot idx ring
// -> tf32 mma -> register-direct vector scatter-add.
// 148 blocks x 512 threads; each block owns a contiguous range of 128-row tiles.
// Ring safety: issue_gather(t) writes idx slot (t+2)&7; with wait_group(1)
// pacing, that slot's readers are iterations t (gather) and t+2 (scatter),
// both after the group containing the write has drained.
// ---------------------------------------------------------------------------
template <bool ROUNDA>
__global__ __launch_bounds__(512, 1)
void conv_tc(const float* __restrict__ x, const float* __restrict__ w,
             const int* __restrict__ idx_in, const int* __restrict__ idx_out,
             float* __restrict__ out, int M, int MT, int TT, int PER)
{
    extern __shared__ float sm[];
    float* Wsm = sm + 2 * A_FLOATS;
    int*   Ism = (int*)(Wsm + W_FLOATS);     // 8 slots x [128 in | 128 out]
    const int tid = threadIdx.x, lane = tid & 31, warp = tid >> 5;

    int t0 = blockIdx.x * PER;
    int t1 = t0 + PER; if (t1 > TT) t1 = TT;
    if (t0 >= t1) return;

    const uint32_t a0u = s2u(sm), a1u = s2u(sm + A_FLOATS);
    const uint32_t idxu = s2u(Ism);

    // synchronous preload of idx for t0, t0+1
    for (int t = t0; t < t0 + 2 && t < t1; t++) {
        int k = t / MT, mt = t - k * MT, m0 = mt * 128;
        int nr = M - m0; if (nr > 128) nr = 128;
        int* slot = Ism + (t & 7) * 256;
        if (tid < 128)      slot[tid] = (tid < nr) ? __ldg(idx_in + (size_t)k * M + m0 + tid) : 0;
        else if (tid < 256) slot[tid] = ((tid - 128) < nr) ? __ldg(idx_out + (size_t)k * M + m0 + (tid - 128)) : 0;
    }
    __syncthreads();

    // gather A for tile t from smem-resident idx + prefetch idx for t+2
    auto issue_gather = [&](int t) {
        int k = t / MT, mt = t - k * MT, m0 = mt * 128;
        int nr = M - m0; if (nr > 128) nr = 128;
        const int* slot = Ism + (t & 7) * 256;
        uint32_t ab = (t & 1) ? a1u : a0u;
        #pragma unroll
        for (int j = 0; j < 8; j++) {
            int id = tid + j * 512;
            int row = id >> 5, seg = id & 31;
            int ok = (row < nr);
            int src = ok ? slot[row] : 0;
            cpa16(ab + (uint32_t)(row * AS + seg * 4) * 4,
                  x + (size_t)src * CCH + seg * 4, ok ? 16 : 0);
        }
        int tn = t + 2;
        if (tn < t1 && tid < 64) {
            int k2 = tn / MT, mt2 = tn - k2 * MT, m02 = mt2 * 128;
            int nr2 = M - m02; if (nr2 > 128) nr2 = 128;
            int r = (tid & 31) * 4;
            const int* g = (tid < 32) ? (idx_in  + (size_t)k2 * M + m02)
                                      : (idx_out + (size_t)k2 * M + m02);
            uint32_t sdst = idxu + (uint32_t)(((tn & 7) * 256) + ((tid < 32) ? 0 : 128) + r) * 4;
            int nb = (r + 4 <= nr2) ? 16 : ((r < nr2) ? (nr2 - r) * 4 : 0);
            cpa16(sdst, g + r, nb);
        }
        asm volatile("cp.async.commit_group;" ::: "memory");
    };

    issue_gather(t0);
    if (t0 + 1 < t1) issue_gather(t0 + 1);

    int kcur = -1;
    const int wm = warp & 3, wn = warp >> 2;   // 4x4 warp grid over 128x128
    const int gr = lane >> 2, tg = lane & 3;

    for (int i = t0; i < t1; i++) {
        int k = i / MT, mt = i - k * MT, m0 = mt * 128;
        int nr = M - m0; if (nr > 128) nr = 128;
        const float* Asm = (i & 1) ? (sm + A_FLOATS) : sm;
        const int* slot = Ism + (i & 7) * 256;

        if (i + 1 < t1) asm volatile("cp.async.wait_group 1;" ::: "memory");
        else            asm volatile("cp.async.wait_group 0;" ::: "memory");
        __syncthreads();

        if (k != kcur) {
            const float* wk = w + (size_t)k * (CCH * CCH);
            #pragma unroll 4
            for (int j = 0; j < 32; j++) {
                int idx = tid + j * 512;
                int cin = idx >> 7, cout = idx & 127;
                Wsm[cout * WSTR + (cin & 3) * 36 + (cin >> 2)] = tf32r(wk[idx]);
            }
            kcur = k;
            __syncthreads();
        }

        float acc[2][4][4];
        #pragma unroll
        for (int a = 0; a < 2; a++)
            #pragma unroll
            for (int b = 0; b < 4; b++)
                #pragma unroll
                for (int c = 0; c < 4; c++) acc[a][b][c] = 0.f;

        const float* arow0 = Asm + (wm * 32 + gr) * AS;

        #pragma unroll
        for (int u = 0; u < 8; u++) {
            float4 bq[4];
            #pragma unroll
            for (int nf = 0; nf < 4; nf++)
                bq[nf] = *reinterpret_cast<const float4*>(
                    Wsm + (wn * 32 + nf * 8 + gr) * WSTR + tg * 36 + u * 4);
            #pragma unroll
            for (int v = 0; v < 2; v++) {
                int kk = (2 * u + v) * 8;
                uint32_t afr[2][4];
                #pragma unroll
                for (int mf = 0; mf < 2; mf++) {
                    const float* ap = arow0 + mf * 16 * AS + kk + tg;
                    if (ROUNDA) {
                        afr[mf][0] = tf32ru(ap[0]);
                        afr[mf][1] = tf32ru(ap[8 * AS]);
                        afr[mf][2] = tf32ru(ap[4]);
                        afr[mf][3] = tf32ru(ap[8 * AS + 4]);
                    } else {
                        afr[mf][0] = __float_as_uint(ap[0]);
                        afr[mf][1] = __float_as_uint(ap[8 * AS]);
                        afr[mf][2] = __float_as_uint(ap[4]);
                        afr[mf][3] = __float_as_uint(ap[8 * AS + 4]);
                    }
                }
                #pragma unroll
                for (int mf = 0; mf < 2; mf++)
                    #pragma unroll
                    for (int nf = 0; nf < 4; nf++) {
                        uint32_t b0 = __float_as_uint(v ? bq[nf].z : bq[nf].x);
                        uint32_t b1 = __float_as_uint(v ? bq[nf].w : bq[nf].y);
                        mma_tf32(acc[mf][nf], afr[mf], b0, b1);
                    }
            }
        }
        __syncthreads();   // all warps done reading Asm (buf will be overwritten)

        if (i + 2 < t1) issue_gather(i + 2);

        // register-direct scatter: pair lanes via shuffle -> red.global.add.v4
        const int* oslot = slot + 128;
        #pragma unroll
        for (int mf = 0; mf < 2; mf++) {
            #pragma unroll
            for (int rh = 0; rh < 2; rh++) {
                int r = wm * 32 + mf * 16 + rh * 8 + gr;
                int dst = (r < nr) ? oslot[r] : -1;
                #pragma unroll
                for (int nf = 0; nf < 4; nf++) {
                    float c0 = acc[mf][nf][rh * 2 + 0];
                    float c1 = acc[mf][nf][rh * 2 + 1];
                    float q0 = __shfl_xor_sync(0xFFFFFFFFu, c0, 1);
                    float q1 = __shfl_xor_sync(0xFFFFFFFFu, c1, 1);
                    if (!(lane & 1) && dst >= 0) {
                        int col = wn * 32 + nf * 8 + (tg >> 1) * 4;
                        red4(out + (size_t)dst * CCH + col, c0, c1, q0, q1);
                    }
                }
            }
        }
    }
}

// ---------------- elementwise passes ----------------
__global__ void bn_apply(const float* __restrict__ t, const float* __restrict__ sb,
                         float* __restrict__ o, int total4)
{
    int i = blockIdx.x * blockDim.x + threadIdx.x;
    if (i >= total4) return;
    float4 v = reinterpret_cast<const float4*>(t)[i];
    int c = (i & 31) * 4;
    v.x = tf32r(fmaxf(fmaf(v.x, sb[c + 0], sb[128 + c + 0]), 0.f));
    v.y = tf32r(fmaxf(fmaf(v.y, sb[c + 1], sb[128 + c + 1]), 0.f));
    v.z = tf32r(fmaxf(fmaf(v.z, sb[c + 2], sb[128 + c + 2]), 0.f));
    v.w = tf32r(fmaxf(fmaf(v.w, sb[c + 3], sb[128 + c + 3]), 0.f));
    reinterpret_cast<float4*>(o)[i] = v;
}

__global__ void bn_stats(const float* __restrict__ t, int N, float* __restrict__ stats)
{
    __shared__ float sh[256], sh2[256];
    const int c = threadIdx.x & 127;
    const int half = threadIdx.x >> 7;
    float s = 0.f, s2 = 0.f;
    for (int r = blockIdx.x * 2 + half; r < N; r += gridDim.x * 2) {
        float v = t[r * CCH + c];
        s += v;
        s2 = fmaf(v, v, s2);
    }
    sh[threadIdx.x] = s; sh2[threadIdx.x] = s2;
    __syncthreads();
    if (threadIdx.x < 128) {
        atomicAdd(&stats[c],       sh[threadIdx.x] + sh[threadIdx.x + 128]);
        atomicAdd(&stats[128 + c], sh2[threadIdx.x] + sh2[threadIdx.x + 128]);
    }
}

__global__ void bn_finalize(const float* __restrict__ stats,
                            const float* __restrict__ gamma,
                            const float* __restrict__ beta,
                            float* __restrict__ sbout, float invN)
{
    int c = threadIdx.x;
    float mean = stats[c] * invN;
    float var  = stats[128 + c] * invN - mean * mean;
    float s    = gamma[c] * rsqrtf(var + 1e-5f);
    sbout[c]       = s;
    sbout[128 + c] = beta[c] - mean * s;
}

__global__ void final_kernel(const float* __restrict__ t2, const float* __restrict__ x,
                             const float* __restrict__ sbin, float* __restrict__ out,
                             int total4)
{
    int i = blockIdx.x * blockDim.x + threadIdx.x;
    if (i >= total4) return;
    float4 v  = reinterpret_cast<const float4*>(t2)[i];
    float4 xi = reinterpret_cast<const float4*>(x)[i];
    int c = (i & 31) * 4;
    float4 o;
    o.x = fmaxf(fmaf(v.x, sbin[c + 0], sbin[128 + c + 0]) + xi.x, 0.f);
    o.y = fmaxf(fmaf(v.y, sbin[c + 1], sbin[128 + c + 1]) + xi.y, 0.f);
    o.z = fmaxf(fmaf(v.z, sbin[c + 2], sbin[128 + c + 2]) + xi.z, 0.f);
    o.w = fmaxf(fmaf(v.w, sbin[c + 3], sbin[128 + c + 3]) + xi.w, 0.f);
    reinterpret_cast<float4*>(out)[i] = o;
}

// ---------------- launch ----------------
extern "C" void kernel_launch(void* const* d_in, const int* in_sizes, int n_in,
                              void* d_out, int out_size)
{
    const float* x      = (const float*)d_in[0];
    const float* w1     = (const float*)d_in[1];
    const float* gamma1 = (const float*)d_in[2];
    const float* beta1  = (const float*)d_in[3];
    const float* w2     = (const float*)d_in[4];
    const float* gamma2 = (const float*)d_in[5];
    const float* beta2  = (const float*)d_in[6];
    const int*   idx_in  = (const int*)d_in[7];
    const int*   idx_out = (const int*)d_in[8];
    float* out = (float*)d_out;

    const int N = in_sizes[0] / CCH;           // 100000
    const int K = in_sizes[1] / (CCH * CCH);   // 27
    const int M = in_sizes[7] / K;             // 50000
    const int MT = (M + 127) / 128;            // m-tiles per offset
    const int TT = K * MT;                     // total tiles
    const int GRID = 148;
    const int PER = (TT + GRID - 1) / GRID;

    cudaStream_t s = 0;

    float *tmp1, *tmp2, *t1a, *stats, *bnsb;
    cudaGetSymbolAddress((void**)&tmp1,  d_tmp1);
    cudaGetSymbolAddress((void**)&tmp2,  d_tmp2);
    cudaGetSymbolAddress((void**)&t1a,   d_t1a);
    cudaGetSymbolAddress((void**)&stats, d_stats);
    cudaGetSymbolAddress((void**)&bnsb,  d_bnsb);

    size_t nb = (size_t)N * CCH * sizeof(float);
    cudaMemsetAsync(tmp1, 0, nb, s);
    cudaMemsetAsync(tmp2, 0, nb, s);
    cudaMemsetAsync(stats, 0, 512 * sizeof(float), s);

    cudaFuncSetAttribute(conv_tc<true>,  cudaFuncAttributeMaxDynamicSharedMemorySize, SMEM_BYTES);
    cudaFuncSetAttribute(conv_tc<false>, cudaFuncAttributeMaxDynamicSharedMemorySize, SMEM_BYTES);

    const int total4 = N * (CCH / 4);
    const float invN = 1.0f / (float)N;

    // conv1 -> BN1 params  (A rounded at fragment load)
    conv_tc<true><<<GRID, 512, SMEM_BYTES, s>>>(x, w1, idx_in, idx_out, tmp1, M, MT, TT, PER);
    bn_stats<<<148, 256, 0, s>>>(tmp1, N, stats);
    bn_finalize<<<1, 128, 0, s>>>(stats, gamma1, beta1, bnsb, invN);

    // bn1 + relu + round -> conv2 input
    bn_apply<<<(total4 + 255) / 256, 256, 0, s>>>(tmp1, bnsb, t1a, total4);

    // conv2 -> BN2 params
    conv_tc<false><<<GRID, 512, SMEM_BYTES, s>>>(t1a, w2, idx_in, idx_out, tmp2, M, MT, TT, PER);
    bn_stats<<<148, 256, 0, s>>>(tmp2, N, stats + 256);
    bn_finalize<<<1, 128, 0, s>>>(stats + 256, gamma2, beta2, bnsb + 256, invN);

    // residual epilogue
    final_kernel<<<(total4 + 255) / 256, 256, 0, s>>>(tmp2, x, bnsb + 256, out, total4);
}

// round 7
// speedup vs baseline: 2.0758x; 1.0361x over previous
#include <cuda_runtime.h>
#include <cstdint>

// Problem shape (dataset-fixed): N=100000 voxels, C=128, K=27 offsets, M=50000 pairs.
#define CCH 128
#define MAXELEM (100000 * 128)

__device__ float d_tmp1[MAXELEM];   // conv1 raw output
__device__ float d_tmp2[MAXELEM];   // conv2 raw output
__device__ float d_t1a[MAXELEM];    // tf32(relu(bn1(tmp1))) (conv2 input)
__device__ float d_part1[148 * 256];
__device__ float d_part2[148 * 256];

#define AS 132            // A tile row stride (floats)
#define WSTR 144          // W tile col stride (floats): 4 q-blocks x 36
#define A_FLOATS (128 * AS)
#define W_FLOATS (128 * WSTR)
#define IDX_INTS (8 * 256)
#define SMEM_FLOATS (2 * A_FLOATS + W_FLOATS + IDX_INTS)
#define SMEM_BYTES (SMEM_FLOATS * 4)   // 217088 B

// ---------------- helpers ----------------
__device__ __forceinline__ float tf32r(float x) {
    uint32_t u; asm("cvt.rna.tf32.f32 %0, %1;" : "=r"(u) : "f"(x));
    return __uint_as_float(u);
}
__device__ __forceinline__ uint32_t tf32ru(float x) {
    uint32_t u; asm("cvt.rna.tf32.f32 %0, %1;" : "=r"(u) : "f"(x));
    return u;
}
__device__ __forceinline__ uint32_t s2u(const void* p) {
    uint32_t a;
    asm("{ .reg .u64 t; cvta.to.shared.u64 t, %1; cvt.u32.u64 %0, t; }" : "=r"(a) : "l"(p));
    return a;
}
__device__ __forceinline__ void mma_tf32(float* d, const uint32_t* a, uint32_t b0, uint32_t b1) {
    asm volatile(
        "mma.sync.aligned.m16n8k8.row.col.f32.tf32.tf32.f32 "
        "{%0,%1,%2,%3}, {%4,%5,%6,%7}, {%8,%9}, {%0,%1,%2,%3};"
        : "+f"(d[0]), "+f"(d[1]), "+f"(d[2]), "+f"(d[3])
        : "r"(a[0]), "r"(a[1]), "r"(a[2]), "r"(a[3]), "r"(b0), "r"(b1));
}
__device__ __forceinline__ void red4(float* p, float a, float b, float c, float d) {
    asm volatile("red.global.add.v4.f32 [%0], {%1,%2,%3,%4};"
                 :: "l"(p), "f"(a), "f"(b), "f"(c), "f"(d) : "memory");
}
__device__ __forceinline__ void cpa16(uint32_t dst, const void* src, int sbytes) {
    asm volatile("cp.async.cg.shared.global [%0], [%1], 16, %2;"
                 :: "r"(dst), "l"(src), "r"(sbytes) : "memory");
}

// ---------------------------------------------------------------------------
// persistent fused conv: cp.async double-buffered gather + 8-slot idx ring
// -> tf32 mma -> lane-balanced register-direct vector scatter-add.
// ---------------------------------------------------------------------------
template <bool ROUNDA>
__global__ __launch_bounds__(512, 1)
void conv_tc(const float* __restrict__ x, const float* __restrict__ w,
             const int* __restrict__ idx_in, const int* __restrict__ idx_out,
             float* __restrict__ out, int M, int MT, int TT, int PER)
{
    extern __shared__ float sm[];
    float* Wsm = sm + 2 * A_FLOATS;
    int*   Ism = (int*)(Wsm + W_FLOATS);     // 8 slots x [128 in | 128 out]
    const int tid = threadIdx.x, lane = tid & 31, warp = tid >> 5;

    int t0 = blockIdx.x * PER;
    int t1 = t0 + PER; if (t1 > TT) t1 = TT;
    if (t0 >= t1) return;

    const uint32_t a0u = s2u(sm), a1u = s2u(sm + A_FLOATS);
    const uint32_t idxu = s2u(Ism);

    // synchronous preload of idx for t0, t0+1
    for (int t = t0; t < t0 + 2 && t < t1; t++) {
        int k = t / MT, mt = t - k * MT, m0 = mt * 128;
        int nr = M - m0; if (nr > 128) nr = 128;
        int* slot = Ism + (t & 7) * 256;
        if (tid < 128)      slot[tid] = (tid < nr) ? __ldg(idx_in + (size_t)k * M + m0 + tid) : 0;
        else if (tid < 256) slot[tid] = ((tid - 128) < nr) ? __ldg(idx_out + (size_t)k * M + m0 + (tid - 128)) : 0;
    }
    __syncthreads();

    // gather A for tile t from smem-resident idx + prefetch idx for t+2
    auto issue_gather = [&](int t) {
        int k = t / MT, mt = t - k * MT, m0 = mt * 128;
        int nr = M - m0; if (nr > 128) nr = 128;
        const int* slot = Ism + (t & 7) * 256;
        uint32_t ab = (t & 1) ? a1u : a0u;
        #pragma unroll
        for (int j = 0; j < 8; j++) {
            int id = tid + j * 512;
            int row = id >> 5, seg = id & 31;
            int ok = (row < nr);
            int src = ok ? slot[row] : 0;
            cpa16(ab + (uint32_t)(row * AS + seg * 4) * 4,
                  x + (size_t)src * CCH + seg * 4, ok ? 16 : 0);
        }
        int tn = t + 2;
        if (tn < t1 && tid < 64) {
            int k2 = tn / MT, mt2 = tn - k2 * MT, m02 = mt2 * 128;
            int nr2 = M - m02; if (nr2 > 128) nr2 = 128;
            int r = (tid & 31) * 4;
            const int* g = (tid < 32) ? (idx_in  + (size_t)k2 * M + m02)
                                      : (idx_out + (size_t)k2 * M + m02);
            uint32_t sdst = idxu + (uint32_t)(((tn & 7) * 256) + ((tid < 32) ? 0 : 128) + r) * 4;
            int nb = (r + 4 <= nr2) ? 16 : ((r < nr2) ? (nr2 - r) * 4 : 0);
            cpa16(sdst, g + r, nb);
        }
        asm volatile("cp.async.commit_group;" ::: "memory");
    };

    issue_gather(t0);
    if (t0 + 1 < t1) issue_gather(t0 + 1);

    int kcur = -1;
    const int wm = warp & 3, wn = warp >> 2;   // 4x4 warp grid over 128x128
    const int gr = lane >> 2, tg = lane & 3;
    const bool oddlane = (lane & 1);

    for (int i = t0; i < t1; i++) {
        int k = i / MT, mt = i - k * MT, m0 = mt * 128;
        int nr = M - m0; if (nr > 128) nr = 128;
        const float* Asm = (i & 1) ? (sm + A_FLOATS) : sm;
        const int* slot = Ism + (i & 7) * 256;

        if (i + 1 < t1) asm volatile("cp.async.wait_group 1;" ::: "memory");
        else            asm volatile("cp.async.wait_group 0;" ::: "memory");
        __syncthreads();

        if (k != kcur) {
            const float* wk = w + (size_t)k * (CCH * CCH);
            #pragma unroll 4
            for (int j = 0; j < 32; j++) {
                int idx = tid + j * 512;
                int cin = idx >> 7, cout = idx & 127;
                Wsm[cout * WSTR + (cin & 3) * 36 + (cin >> 2)] = tf32r(wk[idx]);
            }
            kcur = k;
            __syncthreads();
        }

        float acc[2][4][4];
        #pragma unroll
        for (int a = 0; a < 2; a++)
            #pragma unroll
            for (int b = 0; b < 4; b++)
                #pragma unroll
                for (int c = 0; c < 4; c++) acc[a][b][c] = 0.f;

        const float* arow0 = Asm + (wm * 32 + gr) * AS;

        #pragma unroll
        for (int u = 0; u < 8; u++) {
            float4 bq[4];
            #pragma unroll
            for (int nf = 0; nf < 4; nf++)
                bq[nf] = *reinterpret_cast<const float4*>(
                    Wsm + (wn * 32 + nf * 8 + gr) * WSTR + tg * 36 + u * 4);
            #pragma unroll
            for (int v = 0; v < 2; v++) {
                int kk = (2 * u + v) * 8;
                uint32_t afr[2][4];
                #pragma unroll
                for (int mf = 0; mf < 2; mf++) {
                    const float* ap = arow0 + mf * 16 * AS + kk + tg;
                    if (ROUNDA) {
                        afr[mf][0] = tf32ru(ap[0]);
                        afr[mf][1] = tf32ru(ap[8 * AS]);
                        afr[mf][2] = tf32ru(ap[4]);
                        afr[mf][3] = tf32ru(ap[8 * AS + 4]);
                    } else {
                        afr[mf][0] = __float_as_uint(ap[0]);
                        afr[mf][1] = __float_as_uint(ap[8 * AS]);
                        afr[mf][2] = __float_as_uint(ap[4]);
                        afr[mf][3] = __float_as_uint(ap[8 * AS + 4]);
                    }
                }
                #pragma unroll
                for (int mf = 0; mf < 2; mf++)
                    #pragma unroll
                    for (int nf = 0; nf < 4; nf++) {
                        uint32_t b0 = __float_as_uint(v ? bq[nf].z : bq[nf].x);
                        uint32_t b1 = __float_as_uint(v ? bq[nf].w : bq[nf].y);
                        mma_tf32(acc[mf][nf], afr[mf], b0, b1);
                    }
            }
        }

        // lane-balanced register-direct scatter (before barrier: overlaps
        // other warps' MMA tail). even nf -> even lane issues; odd nf -> odd.
        const int* oslot = slot + 128;
        #pragma unroll
        for (int mf = 0; mf < 2; mf++) {
            #pragma unroll
            for (int rh = 0; rh < 2; rh++) {
                int r = wm * 32 + mf * 16 + rh * 8 + gr;
                int dst = (r < nr) ? oslot[r] : -1;
                #pragma unroll
                for (int nf = 0; nf < 4; nf++) {
                    float c0 = acc[mf][nf][rh * 2 + 0];
                    float c1 = acc[mf][nf][rh * 2 + 1];
                    float q0 = __shfl_xor_sync(0xFFFFFFFFu, c0, 1);
                    float q1 = __shfl_xor_sync(0xFFFFFFFFu, c1, 1);
                    bool mine = (((nf & 1) ^ (lane & 1)) == 0);
                    if (mine && dst >= 0) {
                        float a0 = oddlane ? q0 : c0, a1 = oddlane ? q1 : c1;
                        float a2 = oddlane ? c0 : q0, a3 = oddlane ? c1 : q1;
                        int col = wn * 32 + nf * 8 + (tg & 2) * 2;
                        red4(out + (size_t)dst * CCH + col, a0, a1, a2, a3);
                    }
                }
            }
        }
        __syncthreads();   // all warps done with Asm[buf] before refill

        if (i + 2 < t1) issue_gather(i + 2);
    }
}

// ---------------- BN stats: per-block partials (no atomics) ----------------
__global__ void bn_stats(const float* __restrict__ t, int N, float* __restrict__ part)
{
    __shared__ float sh[512], sh2[512];
    const int c    = threadIdx.x & 127;
    const int quad = threadIdx.x >> 7;            // 0..3
    float s = 0.f, s2 = 0.f;
    for (int r = blockIdx.x * 4 + quad; r < N; r += gridDim.x * 4) {
        float v = t[r * CCH + c];
        s += v;
        s2 = fmaf(v, v, s2);
    }
    sh[threadIdx.x] = s; sh2[threadIdx.x] = s2;
    __syncthreads();
    if (threadIdx.x < 128) {
        float ss  = sh[c]  + sh[c + 128]  + sh[c + 256]  + sh[c + 384];
        float ss2 = sh2[c] + sh2[c + 128] + sh2[c + 256] + sh2[c + 384];
        part[blockIdx.x * 256 + c]       = ss;
        part[blockIdx.x * 256 + 128 + c] = ss2;
    }
}

// reduce partials -> per-channel scale/bias into smem
__device__ __forceinline__ void make_sb(const float* __restrict__ part,
                                        const float* __restrict__ gamma,
                                        const float* __restrict__ beta,
                                        float invN, float* sb)
{
    if (threadIdx.x < 128) {
        int c = threadIdx.x;
        float s = 0.f, s2 = 0.f;
        #pragma unroll 4
        for (int b = 0; b < 148; b++) {
            s  += part[b * 256 + c];
            s2 += part[b * 256 + 128 + c];
        }
        float mean = s * invN;
        float var  = s2 * invN - mean * mean;
        float sc   = gamma[c] * rsqrtf(var + 1e-5f);
        sb[c]       = sc;
        sb[128 + c] = beta[c] - mean * sc;
    }
    __syncthreads();
}

// bn1 + relu + tf32-round (finalize fused)
__global__ void bn_apply(const float* __restrict__ t, const float* __restrict__ part,
                         const float* __restrict__ gamma, const float* __restrict__ beta,
                         float* __restrict__ o, int total4, float invN)
{
    __shared__ float sb[256];
    make_sb(part, gamma, beta, invN, sb);
    for (int i = blockIdx.x * blockDim.x + threadIdx.x; i < total4; i += gridDim.x * blockDim.x) {
        float4 v = reinterpret_cast<const float4*>(t)[i];
        int c = (i & 31) * 4;
        v.x = tf32r(fmaxf(fmaf(v.x, sb[c + 0], sb[128 + c + 0]), 0.f));
        v.y = tf32r(fmaxf(fmaf(v.y, sb[c + 1], sb[128 + c + 1]), 0.f));
        v.z = tf32r(fmaxf(fmaf(v.z, sb[c + 2], sb[128 + c + 2]), 0.f));
        v.w = tf32r(fmaxf(fmaf(v.w, sb[c + 3], sb[128 + c + 3]), 0.f));
        reinterpret_cast<float4*>(o)[i] = v;
    }
}

// out = relu(bn2(conv2) + identity)  (finalize fused)
__global__ void final_kernel(const float* __restrict__ t2, const float* __restrict__ x,
                             const float* __restrict__ part,
                             const float* __restrict__ gamma, const float* __restrict__ beta,
                             float* __restrict__ out, int total4, float invN)
{
    __shared__ float sb[256];
    make_sb(part, gamma, beta, invN, sb);
    for (int i = blockIdx.x * blockDim.x + threadIdx.x; i < total4; i += gridDim.x * blockDim.x) {
        float4 v  = reinterpret_cast<const float4*>(t2)[i];
        float4 xi = reinterpret_cast<const float4*>(x)[i];
        int c = (i & 31) * 4;
        float4 o;
        o.x = fmaxf(fmaf(v.x, sb[c + 0], sb[128 + c + 0]) + xi.x, 0.f);
        o.y = fmaxf(fmaf(v.y, sb[c + 1], sb[128 + c + 1]) + xi.y, 0.f);
        o.z = fmaxf(fmaf(v.z, sb[c + 2], sb[128 + c + 2]) + xi.z, 0.f);
        o.w = fmaxf(fmaf(v.w, sb[c + 3], sb[128 + c + 3]) + xi.w, 0.f);
        reinterpret_cast<float4*>(out)[i] = o;
    }
}

// ---------------- launch ----------------
extern "C" void kernel_launch(void* const* d_in, const int* in_sizes, int n_in,
                              void* d_out, int out_size)
{
    const float* x      = (const float*)d_in[0];
    const float* w1     = (const float*)d_in[1];
    const float* gamma1 = (const float*)d_in[2];
    const float* beta1  = (const float*)d_in[3];
    const float* w2     = (const float*)d_in[4];
    const float* gamma2 = (const float*)d_in[5];
    const float* beta2  = (const float*)d_in[6];
    const int*   idx_in  = (const int*)d_in[7];
    const int*   idx_out = (const int*)d_in[8];
    float* out = (float*)d_out;

    const int N = in_sizes[0] / CCH;           // 100000
    const int K = in_sizes[1] / (CCH * CCH);   // 27
    const int M = in_sizes[7] / K;             // 50000
    const int MT = (M + 127) / 128;            // m-tiles per offset
    const int TT = K * MT;                     // total tiles
    const int GRID = 148;
    const int PER = (TT + GRID - 1) / GRID;

    cudaStream_t s = 0;

    float *tmp1, *tmp2, *t1a, *part1, *part2;
    cudaGetSymbolAddress((void**)&tmp1,  d_tmp1);
    cudaGetSymbolAddress((void**)&tmp2,  d_tmp2);
    cudaGetSymbolAddress((void**)&t1a,   d_t1a);
    cudaGetSymbolAddress((void**)&part1, d_part1);
    cudaGetSymbolAddress((void**)&part2, d_part2);

    size_t nb = (size_t)N * CCH * sizeof(float);
    cudaMemsetAsync(tmp1, 0, nb, s);
    cudaMemsetAsync(tmp2, 0, nb, s);

    cudaFuncSetAttribute(conv_tc<true>,  cudaFuncAttributeMaxDynamicSharedMemorySize, SMEM_BYTES);
    cudaFuncSetAttribute(conv_tc<false>, cudaFuncAttributeMaxDynamicSharedMemorySize, SMEM_BYTES);

    const int total4 = N * (CCH / 4);
    const float invN = 1.0f / (float)N;

    // conv1 -> BN1 partials -> fused apply
    conv_tc<true><<<GRID, 512, SMEM_BYTES, s>>>(x, w1, idx_in, idx_out, tmp1, M, MT, TT, PER);
    bn_stats<<<148, 512, 0, s>>>(tmp1, N, part1);
    bn_apply<<<148, 256, 0, s>>>(tmp1, part1, gamma1, beta1, t1a, total4, invN);

    // conv2 -> BN2 partials -> fused residual epilogue
    conv_tc<false><<<GRID, 512, SMEM_BYTES, s>>>(t1a, w2, idx_in, idx_out, tmp2, M, MT, TT, PER);
    bn_stats<<<148, 512, 0, s>>>(tmp2, N, part2);
    final_kernel<<<148, 256, 0, s>>>(tmp2, x, part2, gamma2, beta2, out, total4, invN);
}

// round 8
// speedup vs baseline: 2.3513x; 1.1327x over previous
#include <cuda_runtime.h>
#include <cstdint>

// Problem shape (dataset-fixed): N=100000 voxels, C=128, K=27 offsets, M=50000 pairs.
#define CCH 128
#define MAXELEM (100000 * 128)

__device__ float d_tmp1[MAXELEM];   // conv1 raw output
__device__ float d_tmp2[MAXELEM];   // conv2 raw output
__device__ float d_t1a[MAXELEM];    // tf32(relu(bn1(tmp1))) (conv2 input)
__device__ float d_part1[148 * 256];
__device__ float d_part2[148 * 256];

#define AS 132                      // A tile row stride (floats)
#define WSTR 144                    // W tile col stride (floats)
#define A64_FLOATS (64 * AS)        // one 64-row half-tile buffer
#define W_FLOATS (128 * WSTR)
// smem: 4 half-tile A buffers (2 per half) + W + 2 idx rings (8 slots x 128 ints)
#define W_OFF   (4 * A64_FLOATS)
#define IDX_OFF (W_OFF + W_FLOATS)
#define SMEM_FLOATS (IDX_OFF + 2 * 8 * 128)
#define SMEM_BYTES (SMEM_FLOATS * 4)   // 217088 B

// ---------------- helpers ----------------
__device__ __forceinline__ float tf32r(float x) {
    uint32_t u; asm("cvt.rna.tf32.f32 %0, %1;" : "=r"(u) : "f"(x));
    return __uint_as_float(u);
}
__device__ __forceinline__ uint32_t tf32ru(float x) {
    uint32_t u; asm("cvt.rna.tf32.f32 %0, %1;" : "=r"(u) : "f"(x));
    return u;
}
__device__ __forceinline__ uint32_t s2u(const void* p) {
    uint32_t a;
    asm("{ .reg .u64 t; cvta.to.shared.u64 t, %1; cvt.u32.u64 %0, t; }" : "=r"(a) : "l"(p));
    return a;
}
__device__ __forceinline__ void barh(int id) {
    asm volatile("bar.sync %0, 256;" :: "r"(id) : "memory");
}
__device__ __forceinline__ void mma_tf32(float* d, const uint32_t* a, uint32_t b0, uint32_t b1) {
    asm volatile(
        "mma.sync.aligned.m16n8k8.row.col.f32.tf32.tf32.f32 "
        "{%0,%1,%2,%3}, {%4,%5,%6,%7}, {%8,%9}, {%0,%1,%2,%3};"
        : "+f"(d[0]), "+f"(d[1]), "+f"(d[2]), "+f"(d[3])
        : "r"(a[0]), "r"(a[1]), "r"(a[2]), "r"(a[3]), "r"(b0), "r"(b1));
}
__device__ __forceinline__ void red4(float* p, float a, float b, float c, float d) {
    asm volatile("red.global.add.v4.f32 [%0], {%1,%2,%3,%4};"
                 :: "l"(p), "f"(a), "f"(b), "f"(c), "f"(d) : "memory");
}
__device__ __forceinline__ void cpa16(uint32_t dst, const void* src, int sbytes) {
    asm volatile("cp.async.cg.shared.global [%0], [%1], 16, %2;"
                 :: "r"(dst), "l"(src), "r"(sbytes) : "memory");
}

// ---------------------------------------------------------------------------
// persistent fused conv, split-block edition:
// 512 threads = 2 independent 256-thread halves. Each super-tile (128 rows)
// is split: half h owns rows [h*64, h*64+64). Each half has its own
// double-buffered 64x132 A tiles, idx ring, cp.async pipeline and named
// barrier, so the halves drift out of phase and overlap MMA vs scatter/gather.
// W (128x144) is shared; k-changes use a full __syncthreads (same iteration
// index in both halves -> no deadlock).
// ---------------------------------------------------------------------------
template <bool ROUNDA>
__global__ __launch_bounds__(512, 1)
void conv_tc(const float* __restrict__ x, const float* __restrict__ w,
             const int* __restrict__ idx_in, const int* __restrict__ idx_out,
             float* __restrict__ out, int M, int SMT, int TT, int PER)
{
    extern __shared__ float sm[];
    float* Wsm = sm + W_OFF;
    int*   Ism = (int*)(sm + IDX_OFF);
    const int tid = threadIdx.x, lane = tid & 31, warp = tid >> 5;
    const int half = warp >> 3;              // 0 or 1
    const int hwarp = warp & 7;              // warp within half
    const int htid = tid & 255;              // thread within half
    const int barid = 1 + half;

    int t0 = blockIdx.x * PER;
    int t1 = t0 + PER; if (t1 > TT) t1 = TT;
    if (t0 >= t1) return;

    float* Ah = sm + half * (2 * A64_FLOATS);          // this half's A buffers
    int*   Ih = Ism + half * (8 * 128);                // this half's idx ring
    const uint32_t ahu = s2u(Ah);
    const uint32_t ihu = s2u(Ih);

    // synchronous preload of idx for t0, t0+1 (this half's 64 rows)
    for (int t = t0; t < t0 + 2 && t < t1; t++) {
        int k = t / SMT, smt = t - k * SMT, m0 = smt * 128 + half * 64;
        int nr = M - m0; if (nr > 64) nr = 64; if (nr < 0) nr = 0;
        int* slot = Ih + (t & 7) * 128;
        if (htid < 64)       slot[htid] = (htid < nr) ? __ldg(idx_in + (size_t)k * M + m0 + htid) : 0;
        else if (htid < 128) slot[htid] = ((htid - 64) < nr) ? __ldg(idx_out + (size_t)k * M + m0 + (htid - 64)) : 0;
    }
    __syncthreads();

    // gather this half's 64 rows for tile t + prefetch idx for t+2
    auto issue_gather = [&](int t) {
        int k = t / SMT, smt = t - k * SMT, m0 = smt * 128 + half * 64;
        int nr = M - m0; if (nr > 64) nr = 64; if (nr < 0) nr = 0;
        const int* slot = Ih + (t & 7) * 128;
        uint32_t ab = ahu + (uint32_t)(t & 1) * (A64_FLOATS * 4);
        #pragma unroll
        for (int j = 0; j < 8; j++) {
            int id = htid + j * 256;
            int row = id >> 5, seg = id & 31;
            int ok = (row < nr);
            int src = ok ? slot[row] : 0;
            cpa16(ab + (uint32_t)(row * AS + seg * 4) * 4,
                  x + (size_t)src * CCH + seg * 4, ok ? 16 : 0);
        }
        int tn = t + 2;
        if (tn < t1 && htid < 32) {
            int k2 = tn / SMT, smt2 = tn - k2 * SMT, m02 = smt2 * 128 + half * 64;
            int nr2 = M - m02; if (nr2 > 64) nr2 = 64; if (nr2 < 0) nr2 = 0;
            int r = (htid & 15) * 4;
            const int* g = (htid < 16) ? (idx_in  + (size_t)k2 * M + m02)
                                       : (idx_out + (size_t)k2 * M + m02);
            uint32_t sdst = ihu + (uint32_t)(((tn & 7) * 128) + ((htid < 16) ? 0 : 64) + r) * 4;
            int nb = (r + 4 <= nr2) ? 16 : ((r < nr2) ? (nr2 - r) * 4 : 0);
            cpa16(sdst, g + r, nb);
        }
        asm volatile("cp.async.commit_group;" ::: "memory");
    };

    issue_gather(t0);
    if (t0 + 1 < t1) issue_gather(t0 + 1);

    int kcur = -1;
    const int wm = hwarp & 1, wn = hwarp >> 1;   // 2x4 warp grid over 64x128
    const int gr = lane >> 2, tg = lane & 3;
    const bool oddlane = (lane & 1);

    for (int i = t0; i < t1; i++) {
        int k = i / SMT, smt = i - k * SMT, m0 = smt * 128 + half * 64;
        int nr = M - m0; if (nr > 64) nr = 64; if (nr < 0) nr = 0;
        const float* Asm = Ah + (i & 1) * A64_FLOATS;
        const int* slot = Ih + (i & 7) * 128;

        if (i + 1 < t1) asm volatile("cp.async.wait_group 1;" ::: "memory");
        else            asm volatile("cp.async.wait_group 0;" ::: "memory");
        barh(barid);

        if (k != kcur) {                       // rare: both halves at same i
            __syncthreads();
            const float* wk = w + (size_t)k * (CCH * CCH);
            #pragma unroll 4
            for (int j = 0; j < 32; j++) {
                int idx = tid + j * 512;
                int cin = idx >> 7, cout = idx & 127;
                Wsm[cout * WSTR + (cin & 3) * 36 + (cin >> 2)] = tf32r(wk[idx]);
            }
            kcur = k;
            __syncthreads();
        }

        float acc[2][4][4];
        #pragma unroll
        for (int a = 0; a < 2; a++)
            #pragma unroll
            for (int b = 0; b < 4; b++)
                #pragma unroll
                for (int c = 0; c < 4; c++) acc[a][b][c] = 0.f;

        const float* arow0 = Asm + (wm * 32 + gr) * AS;

        #pragma unroll
        for (int u = 0; u < 8; u++) {
            float4 bq[4];
            #pragma unroll
            for (int nf = 0; nf < 4; nf++)
                bq[nf] = *reinterpret_cast<const float4*>(
                    Wsm + (wn * 32 + nf * 8 + gr) * WSTR + tg * 36 + u * 4);
            #pragma unroll
            for (int v = 0; v < 2; v++) {
                int kk = (2 * u + v) * 8;
                uint32_t afr[2][4];
                #pragma unroll
                for (int mf = 0; mf < 2; mf++) {
                    const float* ap = arow0 + mf * 16 * AS + kk + tg;
                    if (ROUNDA) {
                        afr[mf][0] = tf32ru(ap[0]);
                        afr[mf][1] = tf32ru(ap[8 * AS]);
                        afr[mf][2] = tf32ru(ap[4]);
                        afr[mf][3] = tf32ru(ap[8 * AS + 4]);
                    } else {
                        afr[mf][0] = __float_as_uint(ap[0]);
                        afr[mf][1] = __float_as_uint(ap[8 * AS]);
                        afr[mf][2] = __float_as_uint(ap[4]);
                        afr[mf][3] = __float_as_uint(ap[8 * AS + 4]);
                    }
                }
                #pragma unroll
                for (int mf = 0; mf < 2; mf++)
                    #pragma unroll
                    for (int nf = 0; nf < 4; nf++) {
                        uint32_t b0 = __float_as_uint(v ? bq[nf].z : bq[nf].x);
                        uint32_t b1 = __float_as_uint(v ? bq[nf].w : bq[nf].y);
                        mma_tf32(acc[mf][nf], afr[mf], b0, b1);
                    }
            }
        }
        barh(barid);                 // this half done reading its A buffer

        if (i + 2 < t1) issue_gather(i + 2);   // overwrite buf (i&1), in flight

        // lane-balanced register-direct scatter overlapping the gather
        const int* oslot = slot + 64;
        #pragma unroll
        for (int mf = 0; mf < 2; mf++) {
            #pragma unroll
            for (int rh = 0; rh < 2; rh++) {
                int r = wm * 32 + mf * 16 + rh * 8 + gr;
                int dst = (r < nr) ? oslot[r] : -1;
                #pragma unroll
                for (int nf = 0; nf < 4; nf++) {
                    float c0 = acc[mf][nf][rh * 2 + 0];
                    float c1 = acc[mf][nf][rh * 2 + 1];
                    float q0 = __shfl_xor_sync(0xFFFFFFFFu, c0, 1);
                    float q1 = __shfl_xor_sync(0xFFFFFFFFu, c1, 1);
                    bool mine = (((nf & 1) ^ (lane & 1)) == 0);
                    if (mine && dst >= 0) {
                        float a0 = oddlane ? q0 : c0, a1 = oddlane ? q1 : c1;
                        float a2 = oddlane ? c0 : q0, a3 = oddlane ? c1 : q1;
                        int col = wn * 32 + nf * 8 + (tg & 2) * 2;
                        red4(out + (size_t)dst * CCH + col, a0, a1, a2, a3);
                    }
                }
            }
        }
    }
}

// ---------------- BN stats: per-block partials (no atomics) ----------------
__global__ void bn_stats(const float* __restrict__ t, int N, float* __restrict__ part)
{
    __shared__ float sh[512], sh2[512];
    const int c    = threadIdx.x & 127;
    const int quad = threadIdx.x >> 7;            // 0..3
    float s = 0.f, s2 = 0.f;
    for (int r = blockIdx.x * 4 + quad; r < N; r += gridDim.x * 4) {
        float v = t[r * CCH + c];
        s += v;
        s2 = fmaf(v, v, s2);
    }
    sh[threadIdx.x] = s; sh2[threadIdx.x] = s2;
    __syncthreads();
    if (threadIdx.x < 128) {
        float ss  = sh[c]  + sh[c + 128]  + sh[c + 256]  + sh[c + 384];
        float ss2 = sh2[c] + sh2[c + 128] + sh2[c + 256] + sh2[c + 384];
        part[blockIdx.x * 256 + c]       = ss;
        part[blockIdx.x * 256 + 128 + c] = ss2;
    }
}

// reduce partials -> per-channel scale/bias into smem
__device__ __forceinline__ void make_sb(const float* __restrict__ part,
                                        const float* __restrict__ gamma,
                                        const float* __restrict__ beta,
                                        float invN, float* sb)
{
    if (threadIdx.x < 128) {
        int c = threadIdx.x;
        float s = 0.f, s2 = 0.f;
        #pragma unroll 4
        for (int b = 0; b < 148; b++) {
            s  += part[b * 256 + c];
            s2 += part[b * 256 + 128 + c];
        }
        float mean = s * invN;
        float var  = s2 * invN - mean * mean;
        float sc   = gamma[c] * rsqrtf(var + 1e-5f);
        sb[c]       = sc;
        sb[128 + c] = beta[c] - mean * sc;
    }
    __syncthreads();
}

// bn1 + relu + tf32-round (finalize fused)
__global__ void bn_apply(const float* __restrict__ t, const float* __restrict__ part,
                         const float* __restrict__ gamma, const float* __restrict__ beta,
                         float* __restrict__ o, int total4, float invN)
{
    __shared__ float sb[256];
    make_sb(part, gamma, beta, invN, sb);
    for (int i = blockIdx.x * blockDim.x + threadIdx.x; i < total4; i += gridDim.x * blockDim.x) {
        float4 v = reinterpret_cast<const float4*>(t)[i];
        int c = (i & 31) * 4;
        v.x = tf32r(fmaxf(fmaf(v.x, sb[c + 0], sb[128 + c + 0]), 0.f));
        v.y = tf32r(fmaxf(fmaf(v.y, sb[c + 1], sb[128 + c + 1]), 0.f));
        v.z = tf32r(fmaxf(fmaf(v.z, sb[c + 2], sb[128 + c + 2]), 0.f));
        v.w = tf32r(fmaxf(fmaf(v.w, sb[c + 3], sb[128 + c + 3]), 0.f));
        reinterpret_cast<float4*>(o)[i] = v;
    }
}

// out = relu(bn2(conv2) + identity)  (finalize fused)
__global__ void final_kernel(const float* __restrict__ t2, const float* __restrict__ x,
                             const float* __restrict__ part,
                             const float* __restrict__ gamma, const float* __restrict__ beta,
                             float* __restrict__ out, int total4, float invN)
{
    __shared__ float sb[256];
    make_sb(part, gamma, beta, invN, sb);
    for (int i = blockIdx.x * blockDim.x + threadIdx.x; i < total4; i += gridDim.x * blockDim.x) {
        float4 v  = reinterpret_cast<const float4*>(t2)[i];
        float4 xi = reinterpret_cast<const float4*>(x)[i];
        int c = (i & 31) * 4;
        float4 o;
        o.x = fmaxf(fmaf(v.x, sb[c + 0], sb[128 + c + 0]) + xi.x, 0.f);
        o.y = fmaxf(fmaf(v.y, sb[c + 1], sb[128 + c + 1]) + xi.y, 0.f);
        o.z = fmaxf(fmaf(v.z, sb[c + 2], sb[128 + c + 2]) + xi.z, 0.f);
        o.w = fmaxf(fmaf(v.w, sb[c + 3], sb[128 + c + 3]) + xi.w, 0.f);
        reinterpret_cast<float4*>(out)[i] = o;
    }
}

// ---------------- launch ----------------
extern "C" void kernel_launch(void* const* d_in, const int* in_sizes, int n_in,
                              void* d_out, int out_size)
{
    const float* x      = (const float*)d_in[0];
    const float* w1     = (const float*)d_in[1];
    const float* gamma1 = (const float*)d_in[2];
    const float* beta1  = (const float*)d_in[3];
    const float* w2     = (const float*)d_in[4];
    const float* gamma2 = (const float*)d_in[5];
    const float* beta2  = (const float*)d_in[6];
    const int*   idx_in  = (const int*)d_in[7];
    const int*   idx_out = (const int*)d_in[8];
    float* out = (float*)d_out;

    const int N = in_sizes[0] / CCH;           // 100000
    const int K = in_sizes[1] / (CCH * CCH);   // 27
    const int M = in_sizes[7] / K;             // 50000
    const int SMT = (M + 127) / 128;           // 128-row super-tiles per offset
    const int TT = K * SMT;                    // total super-tiles
    const int GRID = 148;
    const int PER = (TT + GRID - 1) / GRID;

    cudaStream_t s = 0;

    float *tmp1, *tmp2, *t1a, *part1, *part2;
    cudaGetSymbolAddress((void**)&tmp1,  d_tmp1);
    cudaGetSymbolAddress((void**)&tmp2,  d_tmp2);
    cudaGetSymbolAddress((void**)&t1a,   d_t1a);
    cudaGetSymbolAddress((void**)&part1, d_part1);
    cudaGetSymbolAddress((void**)&part2, d_part2);

    size_t nb = (size_t)N * CCH * sizeof(float);
    cudaMemsetAsync(tmp1, 0, nb, s);
    cudaMemsetAsync(tmp2, 0, nb, s);

    cudaFuncSetAttribute(conv_tc<true>,  cudaFuncAttributeMaxDynamicSharedMemorySize, SMEM_BYTES);
    cudaFuncSetAttribute(conv_tc<false>, cudaFuncAttributeMaxDynamicSharedMemorySize, SMEM_BYTES);

    const int total4 = N * (CCH / 4);
    const float invN = 1.0f / (float)N;

    // conv1 -> BN1 partials -> fused apply
    conv_tc<true><<<GRID, 512, SMEM_BYTES, s>>>(x, w1, idx_in, idx_out, tmp1, M, SMT, TT, PER);
    bn_stats<<<148, 512, 0, s>>>(tmp1, N, part1);
    bn_apply<<<148, 256, 0, s>>>(tmp1, part1, gamma1, beta1, t1a, total4, invN);

    // conv2 -> BN2 partials -> fused residual epilogue
    conv_tc<false><<<GRID, 512, SMEM_BYTES, s>>>(t1a, w2, idx_in, idx_out, tmp2, M, SMT, TT, PER);
    bn_stats<<<148, 512, 0, s>>>(tmp2, N, part2);
    final_kernel<<<148, 256, 0, s>>>(tmp2, x, part2, gamma2, beta2, out, total4, invN);
}